// round 8
// baseline (speedup 1.0000x reference)
#include <cuda_runtime.h>
#include <cstdint>

// DecoderLSTM on B200: batch dim degenerate -> ONE 84-step 2-layer LSTM
// (H=512) across 128 persistent CTAs. R8 structure: layer-0 consumes only the
// 3-float projected point, accumulated via L2 atomics into one 16B line per
// step (single-line v4 poll detect). Warp groups fully decoupled (no
// cross-group barriers). Posts = tagged u64 words, 8x replicated, nanosleep
// backoff. A reset prekernel zeroes exchange state each run.

#define NCTA   128
#define NT     256
#define HDIM   512
#define TSTEPS 84
#define BROWS  128
#define NREP   8

typedef unsigned long long u64t;
typedef unsigned int u32t;

__device__ u64t g_P0[NREP][2][HDIM];              // layer-0 h posts (tag|payload)
__device__ u64t g_P1[NREP][2][HDIM];              // layer-1 h posts
__device__ __align__(16) float g_acc[TSTEPS][4];  // {sum_x, sum_y, sum_z, cnt}

static __device__ __forceinline__ void post64(u64t* p, u32t tag, float h) {
    u64t v = ((u64t)tag << 32) | (u64t)__float_as_uint(h);
    asm volatile("st.relaxed.gpu.global.u64 [%0], %1;" :: "l"(p), "l"(v) : "memory");
}
static __device__ __forceinline__ u64t ldrel(const u64t* p) {
    u64t v;
    asm volatile("ld.relaxed.gpu.global.u64 %0, [%1];" : "=l"(v) : "l"(p) : "memory");
    return v;
}
static __device__ __forceinline__ float4 ldvol4(const float* p) {
    float4 v;
    asm volatile("ld.volatile.global.v4.f32 {%0,%1,%2,%3}, [%4];"
                 : "=f"(v.x), "=f"(v.y), "=f"(v.z), "=f"(v.w) : "l"(p) : "memory");
    return v;
}
static __device__ __forceinline__ void redadd_relaxed(float* p, float v) {
    asm volatile("red.relaxed.gpu.global.add.f32 [%0], %1;" :: "l"(p), "f"(v) : "memory");
}
static __device__ __forceinline__ void redadd_release(float* p, float v) {
    asm volatile("red.release.gpu.global.add.f32 [%0], %1;" :: "l"(p), "f"(v) : "memory");
}
__device__ __forceinline__ float sigm(float z)  { return 1.0f / (1.0f + __expf(-z)); }
__device__ __forceinline__ float tanh_(float z) { return 2.0f / (1.0f + __expf(-2.0f * z)) - 1.0f; }

#define BARS(id, n) asm volatile("bar.sync %0, %1;" :: "r"(id), "r"(n) : "memory")

// Poll 4 tagged words (stride-128, warp-coalesced) with nanosleep backoff.
static __device__ __forceinline__ void poll4(const u64t* arr, int k, u32t tag, float* dst) {
    u64t v0, v1, v2, v3;
    for (;;) {
        v0 = ldrel(arr + k);
        v1 = ldrel(arr + k + 128);
        v2 = ldrel(arr + k + 256);
        v3 = ldrel(arr + k + 384);
        bool ok = ((u32t)(v0 >> 32) == tag) & ((u32t)(v1 >> 32) == tag) &
                  ((u32t)(v2 >> 32) == tag) & ((u32t)(v3 >> 32) == tag);
        if (ok) break;
        __nanosleep(64);
    }
    dst[k]       = __uint_as_float((u32t)v0);
    dst[k + 128] = __uint_as_float((u32t)v1);
    dst[k + 256] = __uint_as_float((u32t)v2);
    dst[k + 384] = __uint_as_float((u32t)v3);
}

__global__ void __launch_bounds__(256, 1) reset_kernel() {
    int i = blockIdx.x * blockDim.x + threadIdx.x;
    u64t* p0 = &g_P0[0][0][0];
    u64t* p1 = &g_P1[0][0][0];
    const int n = NREP * 2 * HDIM;   // 8192
    if (i < n) { p0[i] = 0ull; p1[i] = 0ull; }
    if (i < TSTEPS * 4) reinterpret_cast<float*>(&g_acc[0][0])[i] = 0.0f;
}

__global__ void __launch_bounds__(NT, 1)
lstm_persistent_kernel(const int* __restrict__ seq,
                       const float* __restrict__ Wih0, const float* __restrict__ Whh0,
                       const float* __restrict__ bih0, const float* __restrict__ bhh0,
                       const float* __restrict__ Wih1, const float* __restrict__ Whh1,
                       const float* __restrict__ bih1, const float* __restrict__ bhh1,
                       const float* __restrict__ Wpc,  const float* __restrict__ bpc,
                       float* __restrict__ out)
{
    __shared__ float h0sA[2][HDIM];   // L0's gathered h0
    __shared__ float h0sB[2][HDIM];   // L1's gathered h0
    __shared__ float h1s[2][HDIM];    // L1's gathered h1 (for hoist)
    __shared__ float pts[TSTEPS * 3];
    __shared__ float xbuf[4];         // point(t-1) + bpc, staged by L0 warp 0
    __shared__ float hsl[4];          // L1's local h1 slice for partial
    __shared__ float wpcs[12];        // Wpc[j][4cta+u], j<3, u<4
    __shared__ float bpcs[3];

    const int tid  = threadIdx.x;
    const int w    = tid >> 5;
    const int lane = tid & 31;
    const int cta  = blockIdx.x;
    const int rep  = cta & (NREP - 1);

    if (tid < 12) wpcs[tid] = Wpc[(size_t)(tid >> 2) * HDIM + 4 * cta + (tid & 3)];
    if (tid < 3)  bpcs[tid] = bpc[tid];
    __syncthreads();

    if (w < 4) {
        // ================= layer 0: warp w owns unit 4*cta + w ==============
        const int unit = 4 * cta + w;
        float whh0r[4][16];
        #pragma unroll
        for (int g = 0; g < 4; g++) {
            const float* p = Whh0 + (size_t)(g * HDIM + unit) * HDIM + lane;
            #pragma unroll
            for (int m = 0; m < 16; m++) whh0r[g][m] = p[32 * m];
        }
        float wx[4][3], bz[4];
        if (lane == 0) {
            #pragma unroll
            for (int g = 0; g < 4; g++) {
                int row = g * HDIM + unit;
                wx[g][0] = Wih0[row * 3];
                wx[g][1] = Wih0[row * 3 + 1];
                wx[g][2] = Wih0[row * 3 + 2];
                bz[g] = bih0[row] + bhh0[row];
            }
        }
        float c0 = 0.0f;
        float a0 = 0.f, a1 = 0.f, a2 = 0.f, a3 = 0.f;  // reduced gate sums (lane0 valid)
        const int k = tid;  // 0..127

        for (int t = 0; t < TSTEPS; t++) {
            const int par = t & 1;
            const u32t tag = (u32t)(t >> 1) + 1u;
            // -------- obtain x(t) = point(t-1) + bpc (single-line detect) ----
            if (t > 0) {
                if (w == 0) {
                    const float* ap = &g_acc[t - 1][0];
                    float4 v;
                    for (;;) { v = ldvol4(ap); if (v.w == 128.0f) break; __nanosleep(32); }
                    if (lane == 0) { xbuf[0] = v.x + bpcs[0]; xbuf[1] = v.y + bpcs[1]; xbuf[2] = v.z + bpcs[2]; }
                }
                BARS(1, 128);
            }
            // -------- activation (lane 0 serial) + post h0(t) ---------------
            float hval = 0.0f;
            if (lane == 0) {
                float x0 = 0.f, x1 = 0.f, x2 = 0.f;
                if (t > 0) { x0 = xbuf[0]; x1 = xbuf[1]; x2 = xbuf[2]; }
                float zi = a0 + bz[0] + wx[0][0] * x0 + wx[0][1] * x1 + wx[0][2] * x2;
                float zf = a1 + bz[1] + wx[1][0] * x0 + wx[1][1] * x1 + wx[1][2] * x2;
                float zg = a2 + bz[2] + wx[2][0] * x0 + wx[2][1] * x1 + wx[2][2] * x2;
                float zo = a3 + bz[3] + wx[3][0] * x0 + wx[3][1] * x1 + wx[3][2] * x2;
                c0 = sigm(zf) * c0 + sigm(zi) * tanh_(zg);
                hval = sigm(zo) * tanh_(c0);
            }
            hval = __shfl_sync(0xffffffffu, hval, 0);
            if (lane < NREP) post64(&g_P0[lane][par][unit], tag, hval);
            // -------- off-path: gather full h0(t), precompute Whh0@h0(t) -----
            poll4(g_P0[rep][par], k, tag, h0sA[par]);
            BARS(1, 128);
            a0 = a1 = a2 = a3 = 0.0f;
            const float* hs = h0sA[par];
            #pragma unroll
            for (int m = 0; m < 16; m++) {
                float h = hs[lane + 32 * m];
                a0 += whh0r[0][m] * h;
                a1 += whh0r[1][m] * h;
                a2 += whh0r[2][m] * h;
                a3 += whh0r[3][m] * h;
            }
            #pragma unroll
            for (int off = 16; off; off >>= 1) {
                a0 += __shfl_xor_sync(0xffffffffu, a0, off);
                a1 += __shfl_xor_sync(0xffffffffu, a1, off);
                a2 += __shfl_xor_sync(0xffffffffu, a2, off);
                a3 += __shfl_xor_sync(0xffffffffu, a3, off);
            }
        }
    } else {
        // ================= layer 1: warp 4+u owns unit 4*cta + u ============
        const int u = w - 4;
        const int unit = 4 * cta + u;
        float wih1r[4][16], whh1r[4][16];
        #pragma unroll
        for (int g = 0; g < 4; g++) {
            const float* p1 = Wih1 + (size_t)(g * HDIM + unit) * HDIM + lane;
            const float* p2 = Whh1 + (size_t)(g * HDIM + unit) * HDIM + lane;
            #pragma unroll
            for (int m = 0; m < 16; m++) { wih1r[g][m] = p1[32 * m]; whh1r[g][m] = p2[32 * m]; }
        }
        float bz[4];
        if (lane == 0) {
            #pragma unroll
            for (int g = 0; g < 4; g++) {
                int row = g * HDIM + unit;
                bz[g] = bih1[row] + bhh1[row];
            }
        }
        float c1 = 0.0f;
        float bh0 = 0.f, bh1v = 0.f, bh2 = 0.f, bh3 = 0.f;  // Whh1@h1(t-1), hoisted
        const int k = tid - 128;  // 0..127

        for (int t = 0; t < TSTEPS; t++) {
            const int par = t & 1;
            const u32t tag = (u32t)(t >> 1) + 1u;
            // -------- on-path: gather h0(t), gates, act, post ---------------
            poll4(g_P0[rep][par], k, tag, h0sB[par]);
            BARS(2, 128);
            float a0 = bh0, a1 = bh1v, a2 = bh2, a3 = bh3;
            const float* hn = h0sB[par];
            #pragma unroll
            for (int m = 0; m < 16; m++) {
                float x = hn[lane + 32 * m];
                a0 += wih1r[0][m] * x;
                a1 += wih1r[1][m] * x;
                a2 += wih1r[2][m] * x;
                a3 += wih1r[3][m] * x;
            }
            #pragma unroll
            for (int off = 16; off; off >>= 1) {
                a0 += __shfl_xor_sync(0xffffffffu, a0, off);
                a1 += __shfl_xor_sync(0xffffffffu, a1, off);
                a2 += __shfl_xor_sync(0xffffffffu, a2, off);
                a3 += __shfl_xor_sync(0xffffffffu, a3, off);
            }
            float hval = 0.0f;
            if (lane == 0) {
                float zi = a0 + bz[0];
                float zf = a1 + bz[1];
                float zg = a2 + bz[2];
                float zo = a3 + bz[3];
                c1 = sigm(zf) * c1 + sigm(zi) * tanh_(zg);
                hval = sigm(zo) * tanh_(c1);
            }
            hval = __shfl_sync(0xffffffffu, hval, 0);
            if (lane == 0) hsl[u] = hval;
            if (lane < NREP) post64(&g_P1[lane][par][unit], tag, hval);
            BARS(2, 128);
            // -------- CTA projection partial -> per-step accumulator --------
            if (w == 4 && lane == 0) {
                float h0v = hsl[0], h1v = hsl[1], h2v = hsl[2], h3v = hsl[3];
                float px = wpcs[0] * h0v + wpcs[1] * h1v + wpcs[2]  * h2v + wpcs[3]  * h3v;
                float py = wpcs[4] * h0v + wpcs[5] * h1v + wpcs[6]  * h2v + wpcs[7]  * h3v;
                float pz = wpcs[8] * h0v + wpcs[9] * h1v + wpcs[10] * h2v + wpcs[11] * h3v;
                float* ap = &g_acc[t][0];
                redadd_relaxed(ap + 0, px);
                redadd_relaxed(ap + 1, py);
                redadd_relaxed(ap + 2, pz);
                redadd_release(ap + 3, 1.0f);   // release orders this thread's adds
            }
            // -------- off-path: gather h1(t), hoist Whh1@h1(t) --------------
            if (t < TSTEPS - 1) {
                poll4(g_P1[rep][par], k, tag, h1s[par]);
                BARS(2, 128);
                bh0 = bh1v = bh2 = bh3 = 0.0f;
                const float* hB = h1s[par];
                #pragma unroll
                for (int m = 0; m < 16; m++) {
                    float y = hB[lane + 32 * m];
                    bh0  += whh1r[0][m] * y;
                    bh1v += whh1r[1][m] * y;
                    bh2  += whh1r[2][m] * y;
                    bh3  += whh1r[3][m] * y;
                }
            }
        }
    }
    __syncthreads();

    // ---- stage all points (poll ensures even acc[83] complete) -------------
    if (tid < TSTEPS) {
        const float* ap = &g_acc[tid][0];
        float4 v;
        for (;;) { v = ldvol4(ap); if (v.w == 128.0f) break; __nanosleep(32); }
        pts[3 * tid + 0] = v.x + bpcs[0];
        pts[3 * tid + 1] = v.y + bpcs[1];
        pts[3 * tid + 2] = v.z + bpcs[2];
    }
    __syncthreads();

    // ---- masked broadcast: out[row][t][j] = (t < seq[row]) ? pts[t][j] : 0 --
    const int row0 = cta * BROWS;
    for (int idx = tid; idx < BROWS * 63; idx += NT) {
        int rl = idx / 63;
        int q  = idx - 63 * rl;
        int row = row0 + rl;
        int L = seq[row];
        int e = 4 * q;
        float4 v;
        v.x = ((e    ) / 3 < L) ? pts[e    ] : 0.0f;
        v.y = ((e + 1) / 3 < L) ? pts[e + 1] : 0.0f;
        v.z = ((e + 2) / 3 < L) ? pts[e + 2] : 0.0f;
        v.w = ((e + 3) / 3 < L) ? pts[e + 3] : 0.0f;
        reinterpret_cast<float4*>(out)[(size_t)row * 63 + q] = v;
    }
}

extern "C" void kernel_launch(void* const* d_in, const int* in_sizes, int n_in,
                              void* d_out, int out_size)
{
    // 0 features (unused), 1 seq_lengths, 2 W_ih0, 3 W_hh0, 4 b_ih0, 5 b_hh0,
    // 6 W_ih1, 7 W_hh1, 8 b_ih1, 9 b_hh1, 10 W_pc, 11 b_pc
    (void)in_sizes; (void)n_in; (void)out_size;
    reset_kernel<<<32, 256>>>();
    lstm_persistent_kernel<<<NCTA, NT>>>(
        (const int*)  d_in[1],
        (const float*)d_in[2], (const float*)d_in[3],
        (const float*)d_in[4], (const float*)d_in[5],
        (const float*)d_in[6], (const float*)d_in[7],
        (const float*)d_in[8], (const float*)d_in[9],
        (const float*)d_in[10], (const float*)d_in[11],
        (float*)d_out);
}